// round 17
// baseline (speedup 1.0000x reference)
#include <cuda_runtime.h>

#define BATCH  8
#define SEQ    4096
#define DMODEL 512

// FINAL. Grid = 2048 CTAs x 128 threads; each CTA covers two positions (two
// 64-thread halves), each thread owns 8 contiguous d's (32B, 256-bit ops).
//
// At the floor: the mandatory 67MB fp32 output stream drains at ~4 TB/s
// (HBM3e write-stream ceiling) => ~16.9us; the table is served from L2
// (HBM traffic ~= writes only in every profile). Bench is invariant to occ
// (25-59%), MLP (4-16) and width within a ±0.6us noise band, but under
// controlled ncu conditions this 256-bit variant is consistently fastest
// (17.3us vs ~20us for 128-bit shapes). L2 policy: default reads +
// evict-first stores — both evict_last experiments regressed (R13 +6us on
// reads, R15 +3us on writes).

struct F8 { float f[8]; };

__device__ __forceinline__ F8 ldg_nc_256(const void* p) {
    unsigned a0,a1,a2,a3,a4,a5,a6,a7;
    asm volatile("ld.global.nc.v8.b32 {%0,%1,%2,%3,%4,%5,%6,%7}, [%8];"
                 : "=r"(a0),"=r"(a1),"=r"(a2),"=r"(a3),
                   "=r"(a4),"=r"(a5),"=r"(a6),"=r"(a7) : "l"(p));
    F8 r;
    r.f[0]=__uint_as_float(a0); r.f[1]=__uint_as_float(a1);
    r.f[2]=__uint_as_float(a2); r.f[3]=__uint_as_float(a3);
    r.f[4]=__uint_as_float(a4); r.f[5]=__uint_as_float(a5);
    r.f[6]=__uint_as_float(a6); r.f[7]=__uint_as_float(a7);
    return r;
}

__device__ __forceinline__ void stg_ef_256(void* p, const float* v) {
    asm volatile("st.global.L2::evict_first.v8.b32 [%0], {%1,%2,%3,%4,%5,%6,%7,%8};"
                 :: "l"(p),
                    "r"(__float_as_uint(v[0])), "r"(__float_as_uint(v[1])),
                    "r"(__float_as_uint(v[2])), "r"(__float_as_uint(v[3])),
                    "r"(__float_as_uint(v[4])), "r"(__float_as_uint(v[5])),
                    "r"(__float_as_uint(v[6])), "r"(__float_as_uint(v[7]))
                 : "memory");
}

__global__ void __launch_bounds__(128)
embed_pe_kernel(const int* __restrict__ tokens,
                const float* __restrict__ table,
                float* __restrict__ out)
{
    const int t    = threadIdx.x;
    const int h    = t >> 6;                  // 0/1: which position
    const int lane = t & 63;
    const int d0   = lane << 3;               // 0,8,...,504
    const int s    = (blockIdx.x << 1) + h;   // 0..4095

    // token ids (uniform per half -> broadcast LDG)
    int tok[BATCH];
#pragma unroll
    for (int b = 0; b < BATCH; ++b)
        tok[b] = __ldg(tokens + b * SEQ + s);

    // fire all 8 gathers (32B each), default L2 policy
    F8 e[BATCH];
#pragma unroll
    for (int b = 0; b < BATCH; ++b)
        e[b] = ldg_nc_256(table + (size_t)tok[b] * DMODEL + d0);

    // PE for (s, d0..d0+7) in the shadow of the loads
    const float ps = (float)s;
    float pe[8];
#pragma unroll
    for (int j = 0; j < 8; ++j) {
        const float fi    = (float)(d0 + j);
        // 1/10000^(2*i/D) = exp2(-(2*i/D)*log2(10000))
        const float inv_w = exp2f(fi * (-2.0f / (float)DMODEL) * 13.287712379549449f);
        const float angle = ps * inv_w;
        pe[j] = ((d0 + j) & 1) ? cosf(angle) : sinf(angle);
    }

    // add + one 256-bit evict-first store per row
#pragma unroll
    for (int b = 0; b < BATCH; ++b) {
        float o[8];
#pragma unroll
        for (int j = 0; j < 8; ++j) o[j] = e[b].f[j] + pe[j];
        stg_ef_256(out + ((size_t)(b * SEQ + s)) * DMODEL + d0, o);
    }
}

extern "C" void kernel_launch(void* const* d_in, const int* in_sizes, int n_in,
                              void* d_out, int out_size)
{
    const int*   tokens = (const int*)d_in[0];   // [B, S] int32
    const float* table  = (const float*)d_in[1]; // [VOCAB, D] f32
    float*       out    = (float*)d_out;         // [B, S, D] f32
    (void)in_sizes; (void)n_in; (void)out_size;

    embed_pe_kernel<<<SEQ / 2, 128>>>(tokens, table, out);
}